// round 16
// baseline (speedup 1.0000x reference)
#include <cuda_runtime.h>
#include <cuda_bf16.h>

#define T_STEPS 1000
#define NB 64
#define NH 512
#define NIN 256
#define KSTART 224            // steps done by phase 1 (matched to GEMM duration)

#define NREC 64
#define NGEMM 84
#define NTILES (T_STEPS * 8)  // 8 n-tiles per timestep

// Constants derived exactly as the Python reference does (double math, then fp32 cast)
#define C_MEM  ((float)(0.001 * (1.0 / 1e-2)))     // DT * TAU_MEM_INV   = 0.1
#define C_SYN  ((float)(0.001 * (1.0 / 5e-3)))     // DT * TAU_SYN_INV   = 0.2
#define C_AD   ((float)(0.001 * (1.0 / 800.0)))    // DT * TAU_ADAPT_INV
#define C_JP   ((float)((1.0 / 800.0) * 1.8))      // TAU_ADAPT_INV * BETA

__device__ __align__(16) float g_xin[(size_t)T_STEPS * NB * NH];
__device__ __align__(16) float g_wrecT[(NH + 1) * NH];
__device__ __align__(16) int   g_done[T_STEPS + 4];
__device__ unsigned int        g_tile;
// phase-1 -> phase-2 state handoff
__device__ __align__(16) float g_hz[NB * NH];
__device__ __align__(16) float g_hv[NB * NH];
__device__ __align__(16) float g_hi[NB * NH];
__device__ __align__(16) float g_hb[NB * NH];

// ---------------------------------------------------------------------------
__global__ void transpose_wrec(const float* __restrict__ W) {
    __shared__ float tile[32][33];
    int mb = blockIdx.x * 32;
    int nb = blockIdx.y * 32;
    #pragma unroll
    for (int j = threadIdx.y; j < 32; j += 8)
        tile[j][threadIdx.x] = W[(size_t)(nb + j) * NH + mb + threadIdx.x];
    __syncthreads();
    #pragma unroll
    for (int j = threadIdx.y; j < 32; j += 8)
        g_wrecT[(size_t)(mb + j) * NH + nb + threadIdx.x] = tile[threadIdx.x][j];
}

__global__ void init_aux() {
    int i = blockIdx.x * blockDim.x + threadIdx.x;
    if (i < NH) g_wrecT[(size_t)NH * NH + i] = 0.0f;   // zero pad row
    if (i < T_STEPS + 4) g_done[i] = 0;
    if (i == 0) g_tile = 0u;
}

// ---------------------------------------------------------------------------
// PHASE 1: fused kernel (R8 verbatim, loop bounded at KSTART + state handoff)
// ---------------------------------------------------------------------------
struct GemmSmem {
    float As[32][68];
    float Bs[32][68];
    unsigned tau;
};
struct RecSmem {
    int      list[NH + 24];
    unsigned masks[16];
};
union FusedSmem {
    GemmSmem g;
    RecSmem  r;
};

__global__ void __launch_bounds__(256, 1) fused_phase1(
    const float* __restrict__ X,  const float* __restrict__ Win,
    const float* __restrict__ z0, const float* __restrict__ v0,
    const float* __restrict__ i0, const float* __restrict__ b0,
    float* __restrict__ out) {

    __shared__ FusedSmem sm;
    const int bid = blockIdx.x;
    const int tid = threadIdx.x;

    if (bid >= NREC) {
        // GEMM worker: strictly sequential k, fused FMA (bit-exact)
        const int t  = tid;
        const int lm = t >> 3;
        const int lk = (t & 7) * 4;
        const int tx = t & 15;
        const int ty = t >> 4;

        for (;;) {
            if (tid == 0) sm.g.tau = atomicAdd(&g_tile, 1u);
            __syncthreads();
            const unsigned tau = sm.g.tau;
            if (tau >= (unsigned)NTILES) break;
            const int c  = (int)(tau >> 3);
            const int j  = (int)(tau & 7u);
            const int r0 = c * 64;
            const int n0 = j * 64;

            float acc[4][4];
            #pragma unroll
            for (int i = 0; i < 4; i++)
                #pragma unroll
                for (int q = 0; q < 4; q++) acc[i][q] = 0.0f;

            for (int kt = 0; kt < NIN; kt += 32) {
                #pragma unroll
                for (int h = 0; h < 2; h++) {
                    int m = lm + 32 * h;
                    float4 a = *(const float4*)(X + (size_t)(r0 + m) * NIN + kt + lk);
                    sm.g.As[lk + 0][m] = a.x; sm.g.As[lk + 1][m] = a.y;
                    sm.g.As[lk + 2][m] = a.z; sm.g.As[lk + 3][m] = a.w;
                    float4 bb = *(const float4*)(Win + (size_t)(n0 + m) * NIN + kt + lk);
                    sm.g.Bs[lk + 0][m] = bb.x; sm.g.Bs[lk + 1][m] = bb.y;
                    sm.g.Bs[lk + 2][m] = bb.z; sm.g.Bs[lk + 3][m] = bb.w;
                }
                __syncthreads();

                #pragma unroll
                for (int kk = 0; kk < 32; kk++) {
                    float4 av = *(const float4*)(&sm.g.As[kk][4 * ty]);
                    float4 bv = *(const float4*)(&sm.g.Bs[kk][4 * tx]);
                    float am[4] = {av.x, av.y, av.z, av.w};
                    float bn[4] = {bv.x, bv.y, bv.z, bv.w};
                    #pragma unroll
                    for (int i = 0; i < 4; i++)
                        #pragma unroll
                        for (int q = 0; q < 4; q++)
                            acc[i][q] = __fmaf_rn(am[i], bn[q], acc[i][q]);
                }
                __syncthreads();
            }

            #pragma unroll
            for (int i = 0; i < 4; i++) {
                float4 o = make_float4(acc[i][0], acc[i][1], acc[i][2], acc[i][3]);
                *(float4*)(g_xin + (size_t)(r0 + 4 * ty + i) * NH + n0 + 4 * tx) = o;
            }

            __threadfence();
            __syncthreads();
            if (tid == 0) atomicAdd(&g_done[c], 1);
        }
        return;
    }

    // Recurrent path: steps 0..KSTART-1 (R8 code)
    const int b    = bid;
    const int lane = tid & 31;
    const int wrp  = tid >> 5;
    const int n2   = tid * 2;

    const size_t sb = (size_t)b * NH + n2;
    float2 v  = *(const float2*)(v0 + sb);
    float2 cu = *(const float2*)(i0 + sb);
    float2 ba = *(const float2*)(b0 + sb);
    float2 z  = *(const float2*)(z0 + sb);

    auto build = [&](const float2& zz) -> int {
        unsigned m0 = __ballot_sync(0xffffffffu, zz.x != 0.0f);
        unsigned m1 = __ballot_sync(0xffffffffu, zz.y != 0.0f);
        if (lane == 0) {
            sm.r.masks[2 * wrp + 0] = m0;
            sm.r.masks[2 * wrp + 1] = m1;
        }
        __syncthreads();
        int cnt = 0, mybase = 0;
        #pragma unroll
        for (int w = 0; w < 8; w++) {
            int s = __popc(sm.r.masks[2 * w]) + __popc(sm.r.masks[2 * w + 1]);
            if (w < wrp) mybase += s;
            cnt += s;
        }
        unsigned lt = (1u << lane) - 1u;
        int pos = mybase + __popc(m0 & lt) + __popc(m1 & lt);
        if (m0 & (1u << lane)) sm.r.list[pos++] = n2;
        if (m1 & (1u << lane)) sm.r.list[pos]   = n2 + 1;
        int cntp = ((cnt + 23) / 24) * 24;
        if (cntp == 0) cntp = 24;
        if (tid < cntp - cnt) sm.r.list[cnt + tid] = NH;
        __syncthreads();
        return cntp;
    };

    int cntp = build(z);

    const float* xin_p = g_xin + sb;
    float*       out_p = out + sb;

    int  W = 0;
    int  pfbase = -1;
    int4 pf = make_int4(0, 0, 0, 0);

    for (int t = 0; t < KSTART; t++) {
        if (pfbase >= 0) {
            int f0[4] = {pf.x, pf.y, pf.z, pf.w};
            #pragma unroll
            for (int k2 = 0; k2 < 4; k2++)
                if (pfbase + k2 == W && f0[k2] >= 8) W++;
        }
        if (W <= t) {
            while (W <= t) {
                if (__ldcg(&g_done[W]) >= 8) W++;
            }
        }
        if (W < T_STEPS) {
            pfbase = W & ~3;
            pf = __ldcg((const int4*)&g_done[pfbase]);
        } else {
            pfbase = -1;
        }

        float2 xin = __ldcs((const float2*)xin_p);
        xin_p += NB * NH;

        float2 RA[8], RB[8], RC[8];

        #define LOADB(R, base_k)                                            \
            do {                                                            \
                int4 _a = *(const int4*)(sm.r.list + (base_k));             \
                int4 _b = *(const int4*)(sm.r.list + (base_k) + 4);         \
                (R)[0] = *(const float2*)(g_wrecT + (size_t)_a.x * NH + n2);\
                (R)[1] = *(const float2*)(g_wrecT + (size_t)_a.y * NH + n2);\
                (R)[2] = *(const float2*)(g_wrecT + (size_t)_a.z * NH + n2);\
                (R)[3] = *(const float2*)(g_wrecT + (size_t)_a.w * NH + n2);\
                (R)[4] = *(const float2*)(g_wrecT + (size_t)_b.x * NH + n2);\
                (R)[5] = *(const float2*)(g_wrecT + (size_t)_b.y * NH + n2);\
                (R)[6] = *(const float2*)(g_wrecT + (size_t)_b.z * NH + n2);\
                (R)[7] = *(const float2*)(g_wrecT + (size_t)_b.w * NH + n2);\
            } while (0)

        #define CONSUME(R)                                                          \
            do {                                                                    \
                recx = __fadd_rn(recx, (R)[0].x); recy = __fadd_rn(recy, (R)[0].y); \
                recx = __fadd_rn(recx, (R)[1].x); recy = __fadd_rn(recy, (R)[1].y); \
                recx = __fadd_rn(recx, (R)[2].x); recy = __fadd_rn(recy, (R)[2].y); \
                recx = __fadd_rn(recx, (R)[3].x); recy = __fadd_rn(recy, (R)[3].y); \
                recx = __fadd_rn(recx, (R)[4].x); recy = __fadd_rn(recy, (R)[4].y); \
                recx = __fadd_rn(recx, (R)[5].x); recy = __fadd_rn(recy, (R)[5].y); \
                recx = __fadd_rn(recx, (R)[6].x); recy = __fadd_rn(recy, (R)[6].y); \
                recx = __fadd_rn(recx, (R)[7].x); recy = __fadd_rn(recy, (R)[7].y); \
            } while (0)

        float recx = 0.0f, recy = 0.0f;
        LOADB(RA, 0);
        LOADB(RB, 8);
        LOADB(RC, 16);
        int k = 0;
        #pragma unroll 1
        for (; k + 48 <= cntp; k += 24) {
            CONSUME(RA); LOADB(RA, k + 24);
            CONSUME(RB); LOADB(RB, k + 32);
            CONSUME(RC); LOADB(RC, k + 40);
        }
        CONSUME(RA);
        CONSUME(RB);
        CONSUME(RC);

        #undef LOADB
        #undef CONSUME

        float vd0 = __fmaf_rn(C_MEM, __fadd_rn(__fsub_rn(0.0f, v.x), cu.x), v.x);
        float vd1 = __fmaf_rn(C_MEM, __fadd_rn(__fsub_rn(0.0f, v.y), cu.y), v.y);
        float bd0 = __fmaf_rn(C_AD, __fsub_rn(1.0f, ba.x), ba.x);
        float bd1 = __fmaf_rn(C_AD, __fsub_rn(1.0f, ba.y), ba.y);
        float zz0 = (__fsub_rn(vd0, bd0) > 0.0f) ? 1.0f : 0.0f;
        float zz1 = (__fsub_rn(vd1, bd1) > 0.0f) ? 1.0f : 0.0f;
        v.x = (zz0 != 0.0f) ? 0.0f : __fadd_rn(vd0, 0.0f);
        v.y = (zz1 != 0.0f) ? 0.0f : __fadd_rn(vd1, 0.0f);
        ba.x = __fadd_rn(bd0, (zz0 != 0.0f) ? C_JP : 0.0f);
        ba.y = __fadd_rn(bd1, (zz1 != 0.0f) ? C_JP : 0.0f);
        float id0 = __fmaf_rn(-C_SYN, cu.x, cu.x);
        float id1 = __fmaf_rn(-C_SYN, cu.y, cu.y);
        cu.x = __fadd_rn(__fadd_rn(id0, xin.x), recx);
        cu.y = __fadd_rn(__fadd_rn(id1, xin.y), recy);
        z.x = zz0;
        z.y = zz1;

        __stcs((float2*)out_p, z);
        out_p += NB * NH;

        cntp = build(z);
    }

    // state handoff to phase 2
    *(float2*)(g_hz + sb) = z;
    *(float2*)(g_hv + sb) = v;
    *(float2*)(g_hi + sb) = cu;
    *(float2*)(g_hb + sb) = ba;
}

// ---------------------------------------------------------------------------
// PHASE 2: 2-CTA clusters (64 clusters), 256 threads/CTA, 1 neuron/thread.
// Column-split gather halves L1 bytes/SM; 8 warps restore issue overlap.
// xin fully materialized by phase 1 -> no polling. Mask exchange = proven R10
// DSMEM/mbarrier protocol (early send, double-buffered, 8 arrivals).
// ---------------------------------------------------------------------------
__global__ void __launch_bounds__(256, 1) __cluster_dims__(2, 1, 1)
lsnn_phase2(float* __restrict__ out, int write_tail) {

    const int b    = blockIdx.x >> 1;
    const int rank = blockIdx.x & 1;
    const int tid  = threadIdx.x;
    const int lane = tid & 31;
    const int wrp  = tid >> 5;          // 0..7
    const int col  = rank * 256 + tid;  // this thread's global column/neuron

    __shared__ __align__(16) int       s_list[NH + 24];
    __shared__ __align__(16) unsigned  s_mask[2][16];
    __shared__ __align__(8) unsigned long long s_mb[2];

    if (tid == 0) {
        unsigned mb0, mb1;
        asm volatile("{ .reg .u64 t; cvta.to.shared.u64 t, %1; cvt.u32.u64 %0, t; }"
                     : "=r"(mb0) : "l"(&s_mb[0]));
        asm volatile("{ .reg .u64 t; cvta.to.shared.u64 t, %1; cvt.u32.u64 %0, t; }"
                     : "=r"(mb1) : "l"(&s_mb[1]));
        asm volatile("mbarrier.init.shared.b64 [%0], 8;" :: "r"(mb0) : "memory");
        asm volatile("mbarrier.init.shared.b64 [%0], 8;" :: "r"(mb1) : "memory");
    }
    asm volatile("barrier.cluster.arrive.aligned;" ::: "memory");
    asm volatile("barrier.cluster.wait.aligned;" ::: "memory");

    const size_t sb = (size_t)b * NH + col;
    float v  = g_hv[sb];
    float cu = g_hi[sb];
    float ba = g_hb[sb];
    float z  = g_hz[sb];

    // Send own-half mask word for exchange e (one word per warp, 8 arrivals).
    auto send = [&](float zz, int e) {
        const int p = e & 1;
        unsigned m = __ballot_sync(0xffffffffu, zz != 0.0f);
        if (lane == 0) {
            int widx = rank * 8 + wrp;          // natural global word index
            s_mask[p][widx] = m;                // local copy
            unsigned laddr, raddr, lmb, rmb;
            asm volatile("{ .reg .u64 t; cvta.to.shared.u64 t, %1; cvt.u32.u64 %0, t; }"
                         : "=r"(laddr) : "l"(&s_mask[p][widx]));
            asm volatile("mapa.shared::cluster.u32 %0, %1, %2;"
                         : "=r"(raddr) : "r"(laddr), "r"(rank ^ 1));
            asm volatile("st.shared::cluster.b32 [%0], %1;"
                         :: "r"(raddr), "r"(m) : "memory");
            asm volatile("{ .reg .u64 t; cvta.to.shared.u64 t, %1; cvt.u32.u64 %0, t; }"
                         : "=r"(lmb) : "l"(&s_mb[p]));
            asm volatile("mapa.shared::cluster.u32 %0, %1, %2;"
                         : "=r"(rmb) : "r"(lmb), "r"(rank ^ 1));
            asm volatile("mbarrier.arrive.release.cluster.shared::cluster.b64 _, [%0];"
                         :: "r"(rmb) : "memory");
        }
    };

    // Wait for peer's 8 arrivals, build global ascending spike list (rows 0..511).
    auto waitbuild = [&](int e) -> int {
        const int p = e & 1;
        const unsigned parity = (unsigned)((e >> 1) & 1);
        {
            unsigned lmb;
            asm volatile("{ .reg .u64 t; cvta.to.shared.u64 t, %1; cvt.u32.u64 %0, t; }"
                         : "=r"(lmb) : "l"(&s_mb[p]));
            unsigned done;
            asm volatile(
                "{\n\t"
                ".reg .pred q;\n\t"
                "mbarrier.try_wait.parity.acquire.cluster.shared::cta.b64 q, [%1], %2;\n\t"
                "selp.b32 %0, 1, 0, q;\n\t"
                "}"
                : "=r"(done) : "r"(lmb), "r"(parity) : "memory");
            if (!done) {
                asm volatile(
                    "{\n\t"
                    ".reg .pred Q;\n\t"
                    "W_%=:\n\t"
                    "mbarrier.try_wait.parity.acquire.cluster.shared::cta.b64 Q, [%0], %1, 0x989680;\n\t"
                    "@Q bra.uni D_%=;\n\t"
                    "bra.uni W_%=;\n\t"
                    "D_%=:\n\t"
                    "}"
                    :: "r"(lmb), "r"(parity) : "memory");
            }
        }
        // thread tid owns global bits 2*tid, 2*tid+1
        int myw = tid >> 4;
        int shift = (tid & 15) * 2;
        int pre = 0, total = 0;
        #pragma unroll
        for (int i = 0; i < 16; i++) {
            int c = __popc(s_mask[p][i]);
            if (i < myw) pre += c;
            total += c;
        }
        unsigned word = s_mask[p][myw];
        unsigned nib = (word >> shift) & 3u;
        pre += __popc(word & ((shift ? (1u << shift) : 1u) - 1u));
        int pos = pre;
        if (nib & 1u) s_list[pos++] = 2 * tid;
        if (nib & 2u) s_list[pos]   = 2 * tid + 1;
        int cntp = ((total + 23) / 24) * 24;
        if (cntp == 0) cntp = 24;
        if (tid < cntp - total) s_list[total + tid] = NH;   // zero row: +0.0 exact
        __syncthreads();
        return cntp;
    };

    send(z, 0);
    __syncthreads();
    int cntp = waitbuild(0);

    const float* xin_p = g_xin + (size_t)KSTART * NB * NH + sb;
    float*       out_p = out + (size_t)KSTART * NB * NH + sb;

    for (int t = KSTART; t < T_STEPS; t++) {
        const int e = t - KSTART;

        // ---- early z_t (depends only on state_{t-1}) + early send ----
        float vd = __fmaf_rn(C_MEM, __fadd_rn(__fsub_rn(0.0f, v), cu), v);
        float bd = __fmaf_rn(C_AD, __fsub_rn(1.0f, ba), ba);
        float zz = (__fsub_rn(vd, bd) > 0.0f) ? 1.0f : 0.0f;

        send(zz, e + 1);   // hidden under the gather below

        v  = (zz != 0.0f) ? 0.0f : __fadd_rn(vd, 0.0f);
        ba = __fadd_rn(bd, (zz != 0.0f) ? C_JP : 0.0f);

        float xin = __ldcs(xin_p);
        xin_p += NB * NH;

        // ---- 3-stage pipelined gather (scalar, own column) ----
        float RA[8], RB[8], RC[8];

        #define LOADB(R, base_k)                                   \
            do {                                                   \
                int4 _a = *(const int4*)(s_list + (base_k));       \
                int4 _b = *(const int4*)(s_list + (base_k) + 4);   \
                (R)[0] = g_wrecT[(size_t)_a.x * NH + col];         \
                (R)[1] = g_wrecT[(size_t)_a.y * NH + col];         \
                (R)[2] = g_wrecT[(size_t)_a.z * NH + col];         \
                (R)[3] = g_wrecT[(size_t)_a.w * NH + col];         \
                (R)[4] = g_wrecT[(size_t)_b.x * NH + col];         \
                (R)[5] = g_wrecT[(size_t)_b.y * NH + col];         \
                (R)[6] = g_wrecT[(size_t)_b.z * NH + col];         \
                (R)[7] = g_wrecT[(size_t)_b.w * NH + col];         \
            } while (0)

        #define CONSUME(R)                      \
            do {                                \
                rec = __fadd_rn(rec, (R)[0]);   \
                rec = __fadd_rn(rec, (R)[1]);   \
                rec = __fadd_rn(rec, (R)[2]);   \
                rec = __fadd_rn(rec, (R)[3]);   \
                rec = __fadd_rn(rec, (R)[4]);   \
                rec = __fadd_rn(rec, (R)[5]);   \
                rec = __fadd_rn(rec, (R)[6]);   \
                rec = __fadd_rn(rec, (R)[7]);   \
            } while (0)

        float rec = 0.0f;
        LOADB(RA, 0);
        LOADB(RB, 8);
        LOADB(RC, 16);
        int k = 0;
        #pragma unroll 1
        for (; k + 48 <= cntp; k += 24) {
            CONSUME(RA); LOADB(RA, k + 24);
            CONSUME(RB); LOADB(RB, k + 32);
            CONSUME(RC); LOADB(RC, k + 40);
        }
        CONSUME(RA);
        CONSUME(RB);
        CONSUME(RC);

        #undef LOADB
        #undef CONSUME

        // ---- late i update ----
        float id = __fmaf_rn(-C_SYN, cu, cu);
        cu = __fadd_rn(__fadd_rn(id, xin), rec);
        z = zz;

        __stcs(out_p, z);
        out_p += NB * NH;

        __syncthreads();            // all warps done reading s_list
        cntp = waitbuild(e + 1);    // peer arrival already complete (early send)
    }

    if (write_tail) {
        size_t base = (size_t)T_STEPS * NB * NH;
        out[base + 0 * (size_t)NB * NH + sb] = z;
        out[base + 1 * (size_t)NB * NH + sb] = v;
        out[base + 2 * (size_t)NB * NH + sb] = cu;
        out[base + 3 * (size_t)NB * NH + sb] = ba;
    }

    asm volatile("barrier.cluster.arrive.aligned;" ::: "memory");
    asm volatile("barrier.cluster.wait.aligned;" ::: "memory");
}

// ---------------------------------------------------------------------------
extern "C" void kernel_launch(void* const* d_in, const int* in_sizes, int n_in,
                              void* d_out, int out_size) {
    const float* x     = (const float*)d_in[0];
    const float* z0    = (const float*)d_in[1];
    const float* v0    = (const float*)d_in[2];
    const float* i0    = (const float*)d_in[3];
    const float* b0    = (const float*)d_in[4];
    const float* w_in  = (const float*)d_in[5];
    const float* w_rec = (const float*)d_in[6];
    float* out = (float*)d_out;

    transpose_wrec<<<dim3(16, 16), dim3(32, 8)>>>(w_rec);
    init_aux<<<(T_STEPS + 4 + 255) / 256, 256>>>();

    long long need = (long long)T_STEPS * NB * NH + 4LL * NB * NH;
    int write_tail = ((long long)out_size >= need) ? 1 : 0;

    fused_phase1<<<NREC + NGEMM, 256>>>(x, w_in, z0, v0, i0, b0, out);
    lsnn_phase2<<<NB * 2, 256>>>(out, write_tail);
}

// round 17
// speedup vs baseline: 1.5641x; 1.5641x over previous
#include <cuda_runtime.h>
#include <cuda_bf16.h>

#define T_STEPS 1000
#define NB 64
#define NH 512
#define NIN 256

#define NREC 64
#define NGEMM 84
#define NTILES (T_STEPS * 8)      // 8 n-tiles per timestep (M-tile = 64 rows = one t)

// Constants derived exactly as the Python reference does (double math, then fp32 cast)
#define C_MEM  ((float)(0.001 * (1.0 / 1e-2)))     // DT * TAU_MEM_INV   = 0.1
#define C_SYN  ((float)(0.001 * (1.0 / 5e-3)))     // DT * TAU_SYN_INV   = 0.2
#define C_AD   ((float)(0.001 * (1.0 / 800.0)))    // DT * TAU_ADAPT_INV
#define C_JP   ((float)((1.0 / 800.0) * 1.8))      // TAU_ADAPT_INV * BETA

__device__ __align__(16) float g_xin[(size_t)T_STEPS * NB * NH];
__device__ __align__(16) float g_wrecT[(NH + 1) * NH];
__device__ __align__(16) int   g_done[T_STEPS + 4];   // per-t finished-tile count (8 = ready)
__device__ unsigned int        g_tile;                // dynamic tile counter

// ---------------------------------------------------------------------------
// Transpose w_rec (NH x NH, row-major [n][m]) -> g_wrecT[m][n]
// ---------------------------------------------------------------------------
__global__ void transpose_wrec(const float* __restrict__ W) {
    __shared__ float tile[32][33];
    int mb = blockIdx.x * 32;
    int nb = blockIdx.y * 32;
    #pragma unroll
    for (int j = threadIdx.y; j < 32; j += 8)
        tile[j][threadIdx.x] = W[(size_t)(nb + j) * NH + mb + threadIdx.x];
    __syncthreads();
    #pragma unroll
    for (int j = threadIdx.y; j < 32; j += 8)
        g_wrecT[(size_t)(mb + j) * NH + nb + threadIdx.x] = tile[threadIdx.x][j];
}

__global__ void init_aux() {
    int i = blockIdx.x * blockDim.x + threadIdx.x;
    if (i < NH) g_wrecT[(size_t)NH * NH + i] = 0.0f;   // zero pad row
    if (i < T_STEPS + 4) g_done[i] = 0;
    if (i == 0) g_tile = 0u;
}

// ---------------------------------------------------------------------------
// Fused persistent kernel, grid = 148 CTAs (all resident in one wave):
//   bid <  64 : recurrence for batch b = bid
//   bid >= 64 : GEMM tile worker (dynamic tiles, ordered by timestep)
// ---------------------------------------------------------------------------
struct GemmSmem {
    float As[32][68];
    float Bs[32][68];
    unsigned tau;
};
struct RecSmem {
    int      list[NH + 24];
    unsigned masks[16];
};
union FusedSmem {
    GemmSmem g;
    RecSmem  r;
};

__global__ void __launch_bounds__(256, 1) fused_lsnn(
    const float* __restrict__ X,  const float* __restrict__ Win,
    const float* __restrict__ z0, const float* __restrict__ v0,
    const float* __restrict__ i0, const float* __restrict__ b0,
    float* __restrict__ out, int write_tail) {

    __shared__ FusedSmem sm;
    const int bid = blockIdx.x;
    const int tid = threadIdx.x;

    if (bid >= NREC) {
        // =================== GEMM worker: Y[r,n] = sum_k X[r,k] Win[n,k] ====
        // Strictly sequential k per output element with fused FMA (bit-exact).
        const int t  = tid;
        const int lm = t >> 3;
        const int lk = (t & 7) * 4;
        const int tx = t & 15;
        const int ty = t >> 4;

        for (;;) {
            if (tid == 0) sm.g.tau = atomicAdd(&g_tile, 1u);
            __syncthreads();
            const unsigned tau = sm.g.tau;
            if (tau >= (unsigned)NTILES) break;
            const int c  = (int)(tau >> 3);
            const int j  = (int)(tau & 7u);
            const int r0 = c * 64;
            const int n0 = j * 64;

            float acc[4][4];
            #pragma unroll
            for (int i = 0; i < 4; i++)
                #pragma unroll
                for (int q = 0; q < 4; q++) acc[i][q] = 0.0f;

            for (int kt = 0; kt < NIN; kt += 32) {
                #pragma unroll
                for (int h = 0; h < 2; h++) {
                    int m = lm + 32 * h;
                    float4 a = *(const float4*)(X + (size_t)(r0 + m) * NIN + kt + lk);
                    sm.g.As[lk + 0][m] = a.x; sm.g.As[lk + 1][m] = a.y;
                    sm.g.As[lk + 2][m] = a.z; sm.g.As[lk + 3][m] = a.w;
                    float4 bb = *(const float4*)(Win + (size_t)(n0 + m) * NIN + kt + lk);
                    sm.g.Bs[lk + 0][m] = bb.x; sm.g.Bs[lk + 1][m] = bb.y;
                    sm.g.Bs[lk + 2][m] = bb.z; sm.g.Bs[lk + 3][m] = bb.w;
                }
                __syncthreads();

                #pragma unroll
                for (int kk = 0; kk < 32; kk++) {
                    float4 av = *(const float4*)(&sm.g.As[kk][4 * ty]);
                    float4 bv = *(const float4*)(&sm.g.Bs[kk][4 * tx]);
                    float am[4] = {av.x, av.y, av.z, av.w};
                    float bn[4] = {bv.x, bv.y, bv.z, bv.w};
                    #pragma unroll
                    for (int i = 0; i < 4; i++)
                        #pragma unroll
                        for (int q = 0; q < 4; q++)
                            acc[i][q] = __fmaf_rn(am[i], bn[q], acc[i][q]);
                }
                __syncthreads();
            }

            #pragma unroll
            for (int i = 0; i < 4; i++) {
                float4 o = make_float4(acc[i][0], acc[i][1], acc[i][2], acc[i][3]);
                *(float4*)(g_xin + (size_t)(r0 + 4 * ty + i) * NH + n0 + 4 * tx) = o;
            }

            __threadfence();       // data visible GPU-wide before flag
            __syncthreads();       // all threads fenced before tid0 publishes
            if (tid == 0) atomicAdd(&g_done[c], 1);
        }
        return;
    }

    // ======================= Recurrent path (8 warps, 2 neurons/thread) =====
    const int b    = bid;
    const int lane = tid & 31;
    const int wrp  = tid >> 5;
    const int n2   = tid * 2;

    const size_t sb = (size_t)b * NH + n2;
    float2 v  = *(const float2*)(v0 + sb);
    float2 cu = *(const float2*)(i0 + sb);
    float2 ba = *(const float2*)(b0 + sb);
    float2 z  = *(const float2*)(z0 + sb);

    // Build spike list (ascending neuron index). Pads to a multiple of 24
    // (minimum 24) with the zero row NH. Returns padded count.
    auto build = [&](const float2& zz) -> int {
        unsigned m0 = __ballot_sync(0xffffffffu, zz.x != 0.0f);
        unsigned m1 = __ballot_sync(0xffffffffu, zz.y != 0.0f);
        if (lane == 0) {
            sm.r.masks[2 * wrp + 0] = m0;
            sm.r.masks[2 * wrp + 1] = m1;
        }
        __syncthreads();
        int cnt = 0, mybase = 0;
        #pragma unroll
        for (int w = 0; w < 8; w++) {
            int s = __popc(sm.r.masks[2 * w]) + __popc(sm.r.masks[2 * w + 1]);
            if (w < wrp) mybase += s;
            cnt += s;
        }
        unsigned lt = (1u << lane) - 1u;
        int pos = mybase + __popc(m0 & lt) + __popc(m1 & lt);
        if (m0 & (1u << lane)) sm.r.list[pos++] = n2;
        if (m1 & (1u << lane)) sm.r.list[pos]   = n2 + 1;
        int cntp = ((cnt + 23) / 24) * 24;
        if (cntp == 0) cntp = 24;
        if (tid < cntp - cnt) sm.r.list[cnt + tid] = NH;   // zero row: +0.0 exact
        __syncthreads();
        return cntp;
    };

    int cntp = build(z);

    const float* xin_p = g_xin + sb;
    float*       out_p = out + sb;

    // Readiness watermark W over g_done, advanced by a one-step-stale int4
    // prefetch (latency overlapped with the gather). Blocking probe only when
    // actually behind (startup transient).
    int  W = 0;
    int  pfbase = -1;
    int4 pf = make_int4(0, 0, 0, 0);

    for (int t = 0; t < T_STEPS; t++) {
        // consume last step's prefetch (lanes checked in ascending order)
        if (pfbase >= 0) {
            int f0[4] = {pf.x, pf.y, pf.z, pf.w};
            #pragma unroll
            for (int k2 = 0; k2 < 4; k2++)
                if (pfbase + k2 == W && f0[k2] >= 8) W++;
        }
        if (W <= t) {
            while (W <= t) {
                if (__ldcg(&g_done[W]) >= 8) W++;
            }
        }
        if (W < T_STEPS) {
            pfbase = W & ~3;
            pf = __ldcg((const int4*)&g_done[pfbase]);
        } else {
            pfbase = -1;
        }

        float2 xin = __ldcs((const float2*)xin_p);
        xin_p += NB * NH;

        // ---- gather with register triple-buffer (batches of 8 rows) ----
        float2 RA[8], RB[8], RC[8];

        #define LOADB(R, base_k)                                            \
            do {                                                            \
                int4 _a = *(const int4*)(sm.r.list + (base_k));             \
                int4 _b = *(const int4*)(sm.r.list + (base_k) + 4);         \
                (R)[0] = *(const float2*)(g_wrecT + (size_t)_a.x * NH + n2);\
                (R)[1] = *(const float2*)(g_wrecT + (size_t)_a.y * NH + n2);\
                (R)[2] = *(const float2*)(g_wrecT + (size_t)_a.z * NH + n2);\
                (R)[3] = *(const float2*)(g_wrecT + (size_t)_a.w * NH + n2);\
                (R)[4] = *(const float2*)(g_wrecT + (size_t)_b.x * NH + n2);\
                (R)[5] = *(const float2*)(g_wrecT + (size_t)_b.y * NH + n2);\
                (R)[6] = *(const float2*)(g_wrecT + (size_t)_b.z * NH + n2);\
                (R)[7] = *(const float2*)(g_wrecT + (size_t)_b.w * NH + n2);\
            } while (0)

        #define CONSUME(R)                                                  \
            do {                                                            \
                recx = __fadd_rn(recx, (R)[0].x); recy = __fadd_rn(recy, (R)[0].y); \
                recx = __fadd_rn(recx, (R)[1].x); recy = __fadd_rn(recy, (R)[1].y); \
                recx = __fadd_rn(recx, (R)[2].x); recy = __fadd_rn(recy, (R)[2].y); \
                recx = __fadd_rn(recx, (R)[3].x); recy = __fadd_rn(recy, (R)[3].y); \
                recx = __fadd_rn(recx, (R)[4].x); recy = __fadd_rn(recy, (R)[4].y); \
                recx = __fadd_rn(recx, (R)[5].x); recy = __fadd_rn(recy, (R)[5].y); \
                recx = __fadd_rn(recx, (R)[6].x); recy = __fadd_rn(recy, (R)[6].y); \
                recx = __fadd_rn(recx, (R)[7].x); recy = __fadd_rn(recy, (R)[7].y); \
            } while (0)

        float recx = 0.0f, recy = 0.0f;
        LOADB(RA, 0);
        LOADB(RB, 8);
        LOADB(RC, 16);
        int k = 0;
        #pragma unroll 1
        for (; k + 48 <= cntp; k += 24) {
            CONSUME(RA); LOADB(RA, k + 24);
            CONSUME(RB); LOADB(RB, k + 32);
            CONSUME(RC); LOADB(RC, k + 40);
        }
        CONSUME(RA);
        CONSUME(RB);
        CONSUME(RC);

        #undef LOADB
        #undef CONSUME

        // ---- elementwise LSNN update (FMA-contracted, matches reference) ----
        float vd0 = __fmaf_rn(C_MEM, __fadd_rn(__fsub_rn(0.0f, v.x), cu.x), v.x);
        float vd1 = __fmaf_rn(C_MEM, __fadd_rn(__fsub_rn(0.0f, v.y), cu.y), v.y);
        float bd0 = __fmaf_rn(C_AD, __fsub_rn(1.0f, ba.x), ba.x);
        float bd1 = __fmaf_rn(C_AD, __fsub_rn(1.0f, ba.y), ba.y);
        float zz0 = (__fsub_rn(vd0, bd0) > 0.0f) ? 1.0f : 0.0f;
        float zz1 = (__fsub_rn(vd1, bd1) > 0.0f) ? 1.0f : 0.0f;
        v.x = (zz0 != 0.0f) ? 0.0f : __fadd_rn(vd0, 0.0f);
        v.y = (zz1 != 0.0f) ? 0.0f : __fadd_rn(vd1, 0.0f);
        ba.x = __fadd_rn(bd0, (zz0 != 0.0f) ? C_JP : 0.0f);
        ba.y = __fadd_rn(bd1, (zz1 != 0.0f) ? C_JP : 0.0f);
        float id0 = __fmaf_rn(-C_SYN, cu.x, cu.x);
        float id1 = __fmaf_rn(-C_SYN, cu.y, cu.y);
        cu.x = __fadd_rn(__fadd_rn(id0, xin.x), recx);
        cu.y = __fadd_rn(__fadd_rn(id1, xin.y), recy);
        z.x = zz0;
        z.y = zz1;

        __stcs((float2*)out_p, z);
        out_p += NB * NH;

        cntp = build(z);    // internal syncthreads orders s_list overwrite vs gather
    }

    if (write_tail) {
        size_t base = (size_t)T_STEPS * NB * NH;
        *(float2*)(out + base + 0 * (size_t)NB * NH + sb) = z;
        *(float2*)(out + base + 1 * (size_t)NB * NH + sb) = v;
        *(float2*)(out + base + 2 * (size_t)NB * NH + sb) = cu;
        *(float2*)(out + base + 3 * (size_t)NB * NH + sb) = ba;
    }
}

// ---------------------------------------------------------------------------
extern "C" void kernel_launch(void* const* d_in, const int* in_sizes, int n_in,
                              void* d_out, int out_size) {
    const float* x     = (const float*)d_in[0];
    const float* z0    = (const float*)d_in[1];
    const float* v0    = (const float*)d_in[2];
    const float* i0    = (const float*)d_in[3];
    const float* b0    = (const float*)d_in[4];
    const float* w_in  = (const float*)d_in[5];
    const float* w_rec = (const float*)d_in[6];
    float* out = (float*)d_out;

    transpose_wrec<<<dim3(16, 16), dim3(32, 8)>>>(w_rec);
    init_aux<<<(T_STEPS + 4 + 255) / 256, 256>>>();

    long long need = (long long)T_STEPS * NB * NH + 4LL * NB * NH;
    int write_tail = ((long long)out_size >= need) ? 1 : 0;
    fused_lsnn<<<NREC + NGEMM, 256>>>(x, w_in, z0, v0, i0, b0, out, write_tail);
}